// round 14
// baseline (speedup 1.0000x reference)
#include <cuda_runtime.h>

// HaarWavelet2D level=2, x:(8,64,256,256) fp32 -> (low,high).
// One fused kernel, 64x32 output tile per 256-thread block.
// E/O column-split smem (conflict-free stride-2), clamp-at-load + reflect
// patch for pure downstream indexing. ll1/hi1 interleaved float2 (LDS.64),
// OVERLAID on the xs region (dead after stage 2) -> 32.8KB smem, 7 CTAs/SM.
// Stage 1 uses float2 global loads on interior block columns.
//
// XE: even cols j0-4..j0+34 -> slots 0..19 (slot (c-j0+4)/2), stride 20
// XO: odd  cols j0-3..j0+35 -> slots 0..19 (slot (c-j0+3)/2), stride 20

#define HW 256
#define IMG (HW*HW)
#define INV256 (1.0f/256.0f)

// smem offsets (floats). XO-XE = 1424 ≡ 16 (mod 32).
#define XE 0
#define XO 1424
#define LLE 2848
#define LLO 4228
#define HSE 5608
#define HSO 6908
#define L12 0              // interleaved {ll1,hi1} float2, ALIASES xs region
#define SM_TOT 8208

__device__ __forceinline__ int clampi(int v, int lo, int hi) {
    return v < lo ? lo : (v > hi ? hi : v);
}

__global__ void __launch_bounds__(256, 7) k_fused(const float* __restrict__ x,
                                                  float* __restrict__ out, int nc) {
    __shared__ float sm[SM_TOT];

    const int ch = blockIdx.z;
    const int i0 = blockIdx.y * 64;
    const int j0 = blockIdx.x * 32;
    const int tid = threadIdx.x;
    const float* xc = x + (size_t)ch * IMG;

    // ---------------- stage 1: load x ----------------
    if (blockIdx.x != 0 && blockIdx.x != 7) {
        // interior: cols j0-4..j0+35 all in [0,255]; float2 loads (8B aligned).
        for (int e = tid; e < 70 * 20; e += 256) {
            int u = e / 20, m = e - u * 20;
            int gr = clampi(i0 - 3 + u, 0, 255);
            float2 v2 = *reinterpret_cast<const float2*>(xc + gr * HW + (j0 - 4 + 2 * m));
            sm[XE + u * 20 + m] = v2.x;   // even col j0-4+2m
            sm[XO + u * 20 + m] = v2.y;   // odd  col j0-3+2m
        }
    } else {
        // edge blocks: scalar with clamp + reflect patch.
        for (int e = tid; e < 70 * 38; e += 256) {
            int u = e / 38, v = e - u * 38;
            int gr = clampi(i0 - 3 + u, 0, 255);
            int g = j0 - 3 + v;
            int gc = clampi(g, 0, 255);
            if (g == -1) gc = 1;
            if (g == 256) gc = 254;
            float val = __ldg(xc + gr * HW + gc);
            // v odd -> even col g -> XE slot (v>>1)+1 ; v even -> odd col -> XO slot v>>1
            sm[((v & 1) ? (XE + 1) : XO) + u * 20 + (v >> 1)] = val;
        }
    }
    __syncthreads();

    // ---------------- stage 2: LL (ll0) + hi0, shared reads ----------------
    for (int e = tid; e < 69 * 19; e += 256) {
        int r = e / 19, w = e - r * 19;
        int ro = r * 20, r1 = ro + 20;
        float o0 = sm[XO + ro + w], e0 = sm[XE + ro + w + 1];
        float o1 = sm[XO + r1 + w], e1 = sm[XE + r1 + w + 1];

        // LLO point (odd col cO = j0-3+2w, and cO+1)
        float sA = o0 + e0, dA = o0 - e0;
        float sB = o1 + e1, dB = o1 - e1;
        sm[LLO + ro + w] = 0.25f * (sA + sB);
        bool hrow = (r >= 2) && (r <= 66);
        int hb = (r - 2) * 20;
        if (hrow && w >= 1 && w <= 17)
            sm[HSO + hb + (w - 1)] =
                0.25f * (fabsf(sA - sB) + fabsf(dA + dB) + fabsf(dA - dB));

        if (w <= 17) {
            float p0 = sm[XO + ro + w + 1];
            float p1 = sm[XO + r1 + w + 1];
            // LLE point (even col cE = j0-2+2w, and cE+1)
            float sC = e0 + p0, dC = e0 - p0;
            float sD = e1 + p1, dD = e1 - p1;
            sm[LLE + ro + w] = 0.25f * (sC + sD);
            if (hrow && w >= 1)
                sm[HSE + hb + (w - 1)] =
                    0.25f * (fabsf(sC - sD) + fabsf(dC + dD) + fabsf(dC - dD));
        }
    }
    __syncthreads();

    // ---------------- stage 3: ll1 / hi1 (writes alias dead xs region) ----------------
    const int A0 = (i0 >> 1) - 1;
    const int B0 = (j0 >> 1) - 1;
    float2* l12 = reinterpret_cast<float2*>(sm + L12);
    for (int e = tid; e < 34 * 18; e += 256) {
        int u = e / 18, v = e - u * 18;
        int a = clampi(A0 + u, 0, 127);
        int b = clampi(B0 + v, 0, 127);
        int d = b - B0;
        int rm = (clampi(2 * a - 1, 0, 254) - (i0 - 3)) * 20;
        int r0 = (2 * a - (i0 - 3)) * 20;
        int rp = (clampi(2 * a + 1, 0, 254) - (i0 - 3)) * 20;

        float m_m = sm[LLO + rm + d], m_0 = sm[LLE + rm + d], m_p = sm[LLO + rm + d + 1];
        float c_m = sm[LLO + r0 + d], c_0 = sm[LLE + r0 + d], c_p = sm[LLO + r0 + d + 1];
        float p_m = sm[LLO + rp + d], p_0 = sm[LLE + rp + d], p_p = sm[LLO + rp + d + 1];

        float wy0 = (2 * a + 0.5f) * INV256, wy1 = (2 * a + 1.5f) * INV256;
        float wx0 = (2 * b + 0.5f) * INV256, wx1 = (2 * b + 1.5f) * INV256;

        float Am = wx0 * m_m + (1.0f - wx0) * m_0;
        float Ac = wx0 * c_m + (1.0f - wx0) * c_0;
        float Ap = wx0 * p_m + (1.0f - wx0) * p_0;
        float Bm = wx1 * m_0 + (1.0f - wx1) * m_p;
        float Bc = wx1 * c_0 + (1.0f - wx1) * c_p;
        float Bp = wx1 * p_0 + (1.0f - wx1) * p_p;

        float L00 = wy0 * Am + (1.0f - wy0) * Ac;
        float L01 = wy0 * Bm + (1.0f - wy0) * Bc;
        float L10 = wy1 * Ac + (1.0f - wy1) * Ap;
        float L11 = wy1 * Bc + (1.0f - wy1) * Bp;

        float ll = 0.25f * (L00 + L01 + L10 + L11);
        float lh = 0.25f * (L00 + L01 - L10 - L11);
        float hl = 0.25f * (L00 - L01 + L10 - L11);
        float hh = 0.25f * (L00 - L01 - L10 + L11);
        l12[u * 18 + v] = make_float2(ll, fabsf(lh) + fabsf(hl) + fabsf(hh));
    }
    __syncthreads();

    // ---------------- stage 4: epilogue (2 vertical quads / thread) ----------------
    const int qx = tid & 15;
    const int ph = tid >> 4;                 // 0..15
    const int q = (j0 >> 1) + qx;            // out cols 2q, 2q+1
    const int p0 = (i0 >> 1) + 2 * ph;       // out rows 2p0..2p0+3

    // --- hi0 resize (255->256): 5 rows x 3 cols, 2 row clamps ---
    int s0 = (clampi(2 * p0 - 1, 0, 254) - (i0 - 1)) * 20;
    int s1 = (4 * ph + 1) * 20;
    int s2 = s1 + 20, s3 = s1 + 40;
    int s4 = (clampi(2 * p0 + 3, 0, 254) - (i0 - 1)) * 20;

    float w0 = (2 * q + 0.5f) * INV256;
    float w1 = (2 * q + 1.5f) * INV256;

#define HCL(S, CA, CB)                                                        \
    {                                                                         \
        float ov = sm[HSO + (S) + qx], ev = sm[HSE + (S) + qx];               \
        float o2 = sm[HSO + (S) + qx + 1];                                    \
        CA = w0 * ov + (1.0f - w0) * ev;                                      \
        CB = w1 * ev + (1.0f - w1) * o2;                                      \
    }
    float cA0, cB0, cA1, cB1, cA2, cB2, cA3, cB3, cA4, cB4;
    HCL(s0, cA0, cB0) HCL(s1, cA1, cB1) HCL(s2, cA2, cB2)
    HCL(s3, cA3, cB3) HCL(s4, cA4, cB4)
#undef HCL

    float wy0 = (2 * p0 + 0.5f) * INV256;
    float wy1 = (2 * p0 + 1.5f) * INV256;
    float wy2 = (2 * p0 + 2.5f) * INV256;
    float wy3 = (2 * p0 + 3.5f) * INV256;

    float h0A0 = wy0 * cA0 + (1.0f - wy0) * cA1;
    float h0B0 = wy0 * cB0 + (1.0f - wy0) * cB1;
    float h0A1 = wy1 * cA1 + (1.0f - wy1) * cA2;
    float h0B1 = wy1 * cB1 + (1.0f - wy1) * cB2;
    float h0A2 = wy2 * cA2 + (1.0f - wy2) * cA3;
    float h0B2 = wy2 * cB2 + (1.0f - wy2) * cB3;
    float h0A3 = wy3 * cA3 + (1.0f - wy3) * cA4;
    float h0B3 = wy3 * cB3 + (1.0f - wy3) * cB4;

    // --- ll1/hi1 resize (128->256): float2 taps, 4 rows x 3 cols, pure ---
    const float2* l12c = reinterpret_cast<const float2*>(sm + L12);
    int t0 = 2 * ph * 18 + qx;
    int t1 = t0 + 18, t2 = t0 + 36, t3 = t0 + 54;

#define LERP2(O, WA, A, WB, B)                                                \
    { O.x = (WA) * A.x + (WB) * B.x; O.y = (WA) * A.y + (WB) * B.y; }

    float2 r0m = l12c[t0], r0c = l12c[t0 + 1], r0p = l12c[t0 + 2];
    float2 r1m = l12c[t1], r1c = l12c[t1 + 1], r1p = l12c[t1 + 2];
    float2 r2m = l12c[t2], r2c = l12c[t2 + 1], r2p = l12c[t2 + 2];
    float2 r3m = l12c[t3], r3c = l12c[t3 + 1], r3p = l12c[t3 + 2];

    float2 a0, b0, a1, b1, a2, b2, a3, b3;
    LERP2(a0, 0.25f, r0m, 0.75f, r0c) LERP2(b0, 0.75f, r0c, 0.25f, r0p)
    LERP2(a1, 0.25f, r1m, 0.75f, r1c) LERP2(b1, 0.75f, r1c, 0.25f, r1p)
    LERP2(a2, 0.25f, r2m, 0.75f, r2c) LERP2(b2, 0.75f, r2c, 0.25f, r2p)
    LERP2(a3, 0.25f, r3m, 0.75f, r3c) LERP2(b3, 0.75f, r3c, 0.25f, r3p)

    float2 vA0, vB0, vA1, vB1, vA2, vB2, vA3, vB3;
    LERP2(vA0, 0.25f, a0, 0.75f, a1) LERP2(vB0, 0.25f, b0, 0.75f, b1)
    LERP2(vA1, 0.75f, a1, 0.25f, a2) LERP2(vB1, 0.75f, b1, 0.25f, b2)
    LERP2(vA2, 0.25f, a1, 0.75f, a2) LERP2(vB2, 0.25f, b1, 0.75f, b2)
    LERP2(vA3, 0.75f, a2, 0.25f, a3) LERP2(vB3, 0.75f, b2, 0.25f, b3)
#undef LERP2

    // --- stores: rows 2p0..2p0+3, cols 2q..2q+1 ---
    const size_t nimg = (size_t)nc * IMG;
    float* out_low = out;
    float* out_high = out + nimg;
    size_t base = (size_t)ch * IMG + (size_t)(2 * p0) * HW + 2 * q;

    *reinterpret_cast<float2*>(out_low + base) = make_float2(vA0.x, vB0.x);
    *reinterpret_cast<float2*>(out_low + base + HW) = make_float2(vA1.x, vB1.x);
    *reinterpret_cast<float2*>(out_low + base + 2 * HW) = make_float2(vA2.x, vB2.x);
    *reinterpret_cast<float2*>(out_low + base + 3 * HW) = make_float2(vA3.x, vB3.x);
    *reinterpret_cast<float2*>(out_high + base) =
        make_float2(0.5f * (h0A0 + vA0.y), 0.5f * (h0B0 + vB0.y));
    *reinterpret_cast<float2*>(out_high + base + HW) =
        make_float2(0.5f * (h0A1 + vA1.y), 0.5f * (h0B1 + vB1.y));
    *reinterpret_cast<float2*>(out_high + base + 2 * HW) =
        make_float2(0.5f * (h0A2 + vA2.y), 0.5f * (h0B2 + vB2.y));
    *reinterpret_cast<float2*>(out_high + base + 3 * HW) =
        make_float2(0.5f * (h0A3 + vA3.y), 0.5f * (h0B3 + vB3.y));
}

extern "C" void kernel_launch(void* const* d_in, const int* in_sizes, int n_in,
                              void* d_out, int out_size) {
    const float* x = (const float*)d_in[0];
    float* out = (float*)d_out;
    int nc = in_sizes[0] / IMG;  // 512

    dim3 blk(256);
    dim3 grd(HW / 32, HW / 64, nc);
    k_fused<<<grd, blk>>>(x, out, nc);
}

// round 15
// speedup vs baseline: 1.0082x; 1.0082x over previous
#include <cuda_runtime.h>

// HaarWavelet2D level=2, x:(8,64,256,256) fp32 -> (low,high).
// One fused kernel, 64x32 output tile per 256-thread block.
// E/O column-split smem (conflict-free stride-2), clamp-at-load + reflect
// patch for pure downstream indexing. ll1/hi1 interleaved float2 (LDS.64),
// OVERLAID on the xs region (dead after stage 2) -> 32.8KB smem, 7 CTAs/SM.
// Stage 1 uses float2 global loads on interior block columns.
//
// XE: even cols j0-4..j0+34 -> slots 0..19 (slot (c-j0+4)/2), stride 20
// XO: odd  cols j0-3..j0+35 -> slots 0..19 (slot (c-j0+3)/2), stride 20

#define HW 256
#define IMG (HW*HW)
#define INV256 (1.0f/256.0f)

// smem offsets (floats). XO-XE = 1424 ≡ 16 (mod 32).
#define XE 0
#define XO 1424
#define LLE 2848
#define LLO 4228
#define HSE 5608
#define HSO 6908
#define L12 0              // interleaved {ll1,hi1} float2, ALIASES xs region
#define SM_TOT 8208

__device__ __forceinline__ int clampi(int v, int lo, int hi) {
    return v < lo ? lo : (v > hi ? hi : v);
}

__global__ void __launch_bounds__(256, 7) k_fused(const float* __restrict__ x,
                                                  float* __restrict__ out, int nc) {
    __shared__ float sm[SM_TOT];

    const int ch = blockIdx.z;
    const int i0 = blockIdx.y * 64;
    const int j0 = blockIdx.x * 32;
    const int tid = threadIdx.x;
    const float* xc = x + (size_t)ch * IMG;

    // ---------------- stage 1: load x ----------------
    if (blockIdx.x != 0 && blockIdx.x != 7) {
        // interior: cols j0-4..j0+35 all in [0,255]; float2 loads (8B aligned).
        for (int e = tid; e < 70 * 20; e += 256) {
            int u = e / 20, m = e - u * 20;
            int gr = clampi(i0 - 3 + u, 0, 255);
            float2 v2 = *reinterpret_cast<const float2*>(xc + gr * HW + (j0 - 4 + 2 * m));
            sm[XE + u * 20 + m] = v2.x;   // even col j0-4+2m
            sm[XO + u * 20 + m] = v2.y;   // odd  col j0-3+2m
        }
    } else {
        // edge blocks: scalar with clamp + reflect patch.
        for (int e = tid; e < 70 * 38; e += 256) {
            int u = e / 38, v = e - u * 38;
            int gr = clampi(i0 - 3 + u, 0, 255);
            int g = j0 - 3 + v;
            int gc = clampi(g, 0, 255);
            if (g == -1) gc = 1;
            if (g == 256) gc = 254;
            float val = __ldg(xc + gr * HW + gc);
            // v odd -> even col g -> XE slot (v>>1)+1 ; v even -> odd col -> XO slot v>>1
            sm[((v & 1) ? (XE + 1) : XO) + u * 20 + (v >> 1)] = val;
        }
    }
    __syncthreads();

    // ---------------- stage 2: LL (ll0) + hi0, shared reads ----------------
    for (int e = tid; e < 69 * 19; e += 256) {
        int r = e / 19, w = e - r * 19;
        int ro = r * 20, r1 = ro + 20;
        float o0 = sm[XO + ro + w], e0 = sm[XE + ro + w + 1];
        float o1 = sm[XO + r1 + w], e1 = sm[XE + r1 + w + 1];

        // LLO point (odd col cO = j0-3+2w, and cO+1)
        float sA = o0 + e0, dA = o0 - e0;
        float sB = o1 + e1, dB = o1 - e1;
        sm[LLO + ro + w] = 0.25f * (sA + sB);
        bool hrow = (r >= 2) && (r <= 66);
        int hb = (r - 2) * 20;
        if (hrow && w >= 1 && w <= 17)
            sm[HSO + hb + (w - 1)] =
                0.25f * (fabsf(sA - sB) + fabsf(dA + dB) + fabsf(dA - dB));

        if (w <= 17) {
            float p0 = sm[XO + ro + w + 1];
            float p1 = sm[XO + r1 + w + 1];
            // LLE point (even col cE = j0-2+2w, and cE+1)
            float sC = e0 + p0, dC = e0 - p0;
            float sD = e1 + p1, dD = e1 - p1;
            sm[LLE + ro + w] = 0.25f * (sC + sD);
            if (hrow && w >= 1)
                sm[HSE + hb + (w - 1)] =
                    0.25f * (fabsf(sC - sD) + fabsf(dC + dD) + fabsf(dC - dD));
        }
    }
    __syncthreads();

    // ---------------- stage 3: ll1 / hi1 (writes alias dead xs region) ----------------
    const int A0 = (i0 >> 1) - 1;
    const int B0 = (j0 >> 1) - 1;
    float2* l12 = reinterpret_cast<float2*>(sm + L12);
    for (int e = tid; e < 34 * 18; e += 256) {
        int u = e / 18, v = e - u * 18;
        int a = clampi(A0 + u, 0, 127);
        int b = clampi(B0 + v, 0, 127);
        int d = b - B0;
        int rm = (clampi(2 * a - 1, 0, 254) - (i0 - 3)) * 20;
        int r0 = (2 * a - (i0 - 3)) * 20;
        int rp = (clampi(2 * a + 1, 0, 254) - (i0 - 3)) * 20;

        float m_m = sm[LLO + rm + d], m_0 = sm[LLE + rm + d], m_p = sm[LLO + rm + d + 1];
        float c_m = sm[LLO + r0 + d], c_0 = sm[LLE + r0 + d], c_p = sm[LLO + r0 + d + 1];
        float p_m = sm[LLO + rp + d], p_0 = sm[LLE + rp + d], p_p = sm[LLO + rp + d + 1];

        float wy0 = (2 * a + 0.5f) * INV256, wy1 = (2 * a + 1.5f) * INV256;
        float wx0 = (2 * b + 0.5f) * INV256, wx1 = (2 * b + 1.5f) * INV256;

        float Am = wx0 * m_m + (1.0f - wx0) * m_0;
        float Ac = wx0 * c_m + (1.0f - wx0) * c_0;
        float Ap = wx0 * p_m + (1.0f - wx0) * p_0;
        float Bm = wx1 * m_0 + (1.0f - wx1) * m_p;
        float Bc = wx1 * c_0 + (1.0f - wx1) * c_p;
        float Bp = wx1 * p_0 + (1.0f - wx1) * p_p;

        float L00 = wy0 * Am + (1.0f - wy0) * Ac;
        float L01 = wy0 * Bm + (1.0f - wy0) * Bc;
        float L10 = wy1 * Ac + (1.0f - wy1) * Ap;
        float L11 = wy1 * Bc + (1.0f - wy1) * Bp;

        float ll = 0.25f * (L00 + L01 + L10 + L11);
        float lh = 0.25f * (L00 + L01 - L10 - L11);
        float hl = 0.25f * (L00 - L01 + L10 - L11);
        float hh = 0.25f * (L00 - L01 - L10 + L11);
        l12[u * 18 + v] = make_float2(ll, fabsf(lh) + fabsf(hl) + fabsf(hh));
    }
    __syncthreads();

    // ---------------- stage 4: epilogue (2 vertical quads / thread) ----------------
    const int qx = tid & 15;
    const int ph = tid >> 4;                 // 0..15
    const int q = (j0 >> 1) + qx;            // out cols 2q, 2q+1
    const int p0 = (i0 >> 1) + 2 * ph;       // out rows 2p0..2p0+3

    // --- hi0 resize (255->256): 5 rows x 3 cols, 2 row clamps ---
    int s0 = (clampi(2 * p0 - 1, 0, 254) - (i0 - 1)) * 20;
    int s1 = (4 * ph + 1) * 20;
    int s2 = s1 + 20, s3 = s1 + 40;
    int s4 = (clampi(2 * p0 + 3, 0, 254) - (i0 - 1)) * 20;

    float w0 = (2 * q + 0.5f) * INV256;
    float w1 = (2 * q + 1.5f) * INV256;

#define HCL(S, CA, CB)                                                        \
    {                                                                         \
        float ov = sm[HSO + (S) + qx], ev = sm[HSE + (S) + qx];               \
        float o2 = sm[HSO + (S) + qx + 1];                                    \
        CA = w0 * ov + (1.0f - w0) * ev;                                      \
        CB = w1 * ev + (1.0f - w1) * o2;                                      \
    }
    float cA0, cB0, cA1, cB1, cA2, cB2, cA3, cB3, cA4, cB4;
    HCL(s0, cA0, cB0) HCL(s1, cA1, cB1) HCL(s2, cA2, cB2)
    HCL(s3, cA3, cB3) HCL(s4, cA4, cB4)
#undef HCL

    float wy0 = (2 * p0 + 0.5f) * INV256;
    float wy1 = (2 * p0 + 1.5f) * INV256;
    float wy2 = (2 * p0 + 2.5f) * INV256;
    float wy3 = (2 * p0 + 3.5f) * INV256;

    float h0A0 = wy0 * cA0 + (1.0f - wy0) * cA1;
    float h0B0 = wy0 * cB0 + (1.0f - wy0) * cB1;
    float h0A1 = wy1 * cA1 + (1.0f - wy1) * cA2;
    float h0B1 = wy1 * cB1 + (1.0f - wy1) * cB2;
    float h0A2 = wy2 * cA2 + (1.0f - wy2) * cA3;
    float h0B2 = wy2 * cB2 + (1.0f - wy2) * cB3;
    float h0A3 = wy3 * cA3 + (1.0f - wy3) * cA4;
    float h0B3 = wy3 * cB3 + (1.0f - wy3) * cB4;

    // --- ll1/hi1 resize (128->256): float2 taps, 4 rows x 3 cols, pure ---
    const float2* l12c = reinterpret_cast<const float2*>(sm + L12);
    int t0 = 2 * ph * 18 + qx;
    int t1 = t0 + 18, t2 = t0 + 36, t3 = t0 + 54;

#define LERP2(O, WA, A, WB, B)                                                \
    { O.x = (WA) * A.x + (WB) * B.x; O.y = (WA) * A.y + (WB) * B.y; }

    float2 r0m = l12c[t0], r0c = l12c[t0 + 1], r0p = l12c[t0 + 2];
    float2 r1m = l12c[t1], r1c = l12c[t1 + 1], r1p = l12c[t1 + 2];
    float2 r2m = l12c[t2], r2c = l12c[t2 + 1], r2p = l12c[t2 + 2];
    float2 r3m = l12c[t3], r3c = l12c[t3 + 1], r3p = l12c[t3 + 2];

    float2 a0, b0, a1, b1, a2, b2, a3, b3;
    LERP2(a0, 0.25f, r0m, 0.75f, r0c) LERP2(b0, 0.75f, r0c, 0.25f, r0p)
    LERP2(a1, 0.25f, r1m, 0.75f, r1c) LERP2(b1, 0.75f, r1c, 0.25f, r1p)
    LERP2(a2, 0.25f, r2m, 0.75f, r2c) LERP2(b2, 0.75f, r2c, 0.25f, r2p)
    LERP2(a3, 0.25f, r3m, 0.75f, r3c) LERP2(b3, 0.75f, r3c, 0.25f, r3p)

    float2 vA0, vB0, vA1, vB1, vA2, vB2, vA3, vB3;
    LERP2(vA0, 0.25f, a0, 0.75f, a1) LERP2(vB0, 0.25f, b0, 0.75f, b1)
    LERP2(vA1, 0.75f, a1, 0.25f, a2) LERP2(vB1, 0.75f, b1, 0.25f, b2)
    LERP2(vA2, 0.25f, a1, 0.75f, a2) LERP2(vB2, 0.25f, b1, 0.75f, b2)
    LERP2(vA3, 0.75f, a2, 0.25f, a3) LERP2(vB3, 0.75f, b2, 0.25f, b3)
#undef LERP2

    // --- stores: rows 2p0..2p0+3, cols 2q..2q+1 ---
    const size_t nimg = (size_t)nc * IMG;
    float* out_low = out;
    float* out_high = out + nimg;
    size_t base = (size_t)ch * IMG + (size_t)(2 * p0) * HW + 2 * q;

    *reinterpret_cast<float2*>(out_low + base) = make_float2(vA0.x, vB0.x);
    *reinterpret_cast<float2*>(out_low + base + HW) = make_float2(vA1.x, vB1.x);
    *reinterpret_cast<float2*>(out_low + base + 2 * HW) = make_float2(vA2.x, vB2.x);
    *reinterpret_cast<float2*>(out_low + base + 3 * HW) = make_float2(vA3.x, vB3.x);
    *reinterpret_cast<float2*>(out_high + base) =
        make_float2(0.5f * (h0A0 + vA0.y), 0.5f * (h0B0 + vB0.y));
    *reinterpret_cast<float2*>(out_high + base + HW) =
        make_float2(0.5f * (h0A1 + vA1.y), 0.5f * (h0B1 + vB1.y));
    *reinterpret_cast<float2*>(out_high + base + 2 * HW) =
        make_float2(0.5f * (h0A2 + vA2.y), 0.5f * (h0B2 + vB2.y));
    *reinterpret_cast<float2*>(out_high + base + 3 * HW) =
        make_float2(0.5f * (h0A3 + vA3.y), 0.5f * (h0B3 + vB3.y));
}

extern "C" void kernel_launch(void* const* d_in, const int* in_sizes, int n_in,
                              void* d_out, int out_size) {
    const float* x = (const float*)d_in[0];
    float* out = (float*)d_out;
    int nc = in_sizes[0] / IMG;  // 512

    dim3 blk(256);
    dim3 grd(HW / 32, HW / 64, nc);
    k_fused<<<grd, blk>>>(x, out, nc);
}

// round 16
// speedup vs baseline: 1.0084x; 1.0002x over previous
#include <cuda_runtime.h>

// HaarWavelet2D level=2, x:(8,64,256,256) fp32 -> (low,high).
// One fused kernel, 64x32 output tile per 256-thread block.
// E/O column-split smem (conflict-free stride-2), clamp-at-load + reflect
// patch for pure downstream indexing. ll1/hi1 interleaved float2 (LDS.64),
// OVERLAID on the xs region (dead after stage 2) -> 32.8KB smem, 7 CTAs/SM.
// Stage 1 uses float2 global loads on interior block columns.
//
// XE: even cols j0-4..j0+34 -> slots 0..19 (slot (c-j0+4)/2), stride 20
// XO: odd  cols j0-3..j0+35 -> slots 0..19 (slot (c-j0+3)/2), stride 20

#define HW 256
#define IMG (HW*HW)
#define INV256 (1.0f/256.0f)

// smem offsets (floats). XO-XE = 1424 ≡ 16 (mod 32).
#define XE 0
#define XO 1424
#define LLE 2848
#define LLO 4228
#define HSE 5608
#define HSO 6908
#define L12 0              // interleaved {ll1,hi1} float2, ALIASES xs region
#define SM_TOT 8208

__device__ __forceinline__ int clampi(int v, int lo, int hi) {
    return v < lo ? lo : (v > hi ? hi : v);
}

__global__ void __launch_bounds__(256, 7) k_fused(const float* __restrict__ x,
                                                  float* __restrict__ out, int nc) {
    __shared__ float sm[SM_TOT];

    const int ch = blockIdx.z;
    const int i0 = blockIdx.y * 64;
    const int j0 = blockIdx.x * 32;
    const int tid = threadIdx.x;
    const float* xc = x + (size_t)ch * IMG;

    // ---------------- stage 1: load x ----------------
    if (blockIdx.x != 0 && blockIdx.x != 7) {
        // interior: cols j0-4..j0+35 all in [0,255]; float2 loads (8B aligned).
        for (int e = tid; e < 70 * 20; e += 256) {
            int u = e / 20, m = e - u * 20;
            int gr = clampi(i0 - 3 + u, 0, 255);
            float2 v2 = *reinterpret_cast<const float2*>(xc + gr * HW + (j0 - 4 + 2 * m));
            sm[XE + u * 20 + m] = v2.x;   // even col j0-4+2m
            sm[XO + u * 20 + m] = v2.y;   // odd  col j0-3+2m
        }
    } else {
        // edge blocks: scalar with clamp + reflect patch.
        for (int e = tid; e < 70 * 38; e += 256) {
            int u = e / 38, v = e - u * 38;
            int gr = clampi(i0 - 3 + u, 0, 255);
            int g = j0 - 3 + v;
            int gc = clampi(g, 0, 255);
            if (g == -1) gc = 1;
            if (g == 256) gc = 254;
            float val = __ldg(xc + gr * HW + gc);
            // v odd -> even col g -> XE slot (v>>1)+1 ; v even -> odd col -> XO slot v>>1
            sm[((v & 1) ? (XE + 1) : XO) + u * 20 + (v >> 1)] = val;
        }
    }
    __syncthreads();

    // ---------------- stage 2: LL (ll0) + hi0, shared reads ----------------
    for (int e = tid; e < 69 * 19; e += 256) {
        int r = e / 19, w = e - r * 19;
        int ro = r * 20, r1 = ro + 20;
        float o0 = sm[XO + ro + w], e0 = sm[XE + ro + w + 1];
        float o1 = sm[XO + r1 + w], e1 = sm[XE + r1 + w + 1];

        // LLO point (odd col cO = j0-3+2w, and cO+1)
        float sA = o0 + e0, dA = o0 - e0;
        float sB = o1 + e1, dB = o1 - e1;
        sm[LLO + ro + w] = 0.25f * (sA + sB);
        bool hrow = (r >= 2) && (r <= 66);
        int hb = (r - 2) * 20;
        if (hrow && w >= 1 && w <= 17)
            sm[HSO + hb + (w - 1)] =
                0.25f * (fabsf(sA - sB) + fabsf(dA + dB) + fabsf(dA - dB));

        if (w <= 17) {
            float p0 = sm[XO + ro + w + 1];
            float p1 = sm[XO + r1 + w + 1];
            // LLE point (even col cE = j0-2+2w, and cE+1)
            float sC = e0 + p0, dC = e0 - p0;
            float sD = e1 + p1, dD = e1 - p1;
            sm[LLE + ro + w] = 0.25f * (sC + sD);
            if (hrow && w >= 1)
                sm[HSE + hb + (w - 1)] =
                    0.25f * (fabsf(sC - sD) + fabsf(dC + dD) + fabsf(dC - dD));
        }
    }
    __syncthreads();

    // ---------------- stage 3: ll1 / hi1 (writes alias dead xs region) ----------------
    const int A0 = (i0 >> 1) - 1;
    const int B0 = (j0 >> 1) - 1;
    float2* l12 = reinterpret_cast<float2*>(sm + L12);
    for (int e = tid; e < 34 * 18; e += 256) {
        int u = e / 18, v = e - u * 18;
        int a = clampi(A0 + u, 0, 127);
        int b = clampi(B0 + v, 0, 127);
        int d = b - B0;
        int rm = (clampi(2 * a - 1, 0, 254) - (i0 - 3)) * 20;
        int r0 = (2 * a - (i0 - 3)) * 20;
        int rp = (clampi(2 * a + 1, 0, 254) - (i0 - 3)) * 20;

        float m_m = sm[LLO + rm + d], m_0 = sm[LLE + rm + d], m_p = sm[LLO + rm + d + 1];
        float c_m = sm[LLO + r0 + d], c_0 = sm[LLE + r0 + d], c_p = sm[LLO + r0 + d + 1];
        float p_m = sm[LLO + rp + d], p_0 = sm[LLE + rp + d], p_p = sm[LLO + rp + d + 1];

        float wy0 = (2 * a + 0.5f) * INV256, wy1 = (2 * a + 1.5f) * INV256;
        float wx0 = (2 * b + 0.5f) * INV256, wx1 = (2 * b + 1.5f) * INV256;

        float Am = wx0 * m_m + (1.0f - wx0) * m_0;
        float Ac = wx0 * c_m + (1.0f - wx0) * c_0;
        float Ap = wx0 * p_m + (1.0f - wx0) * p_0;
        float Bm = wx1 * m_0 + (1.0f - wx1) * m_p;
        float Bc = wx1 * c_0 + (1.0f - wx1) * c_p;
        float Bp = wx1 * p_0 + (1.0f - wx1) * p_p;

        float L00 = wy0 * Am + (1.0f - wy0) * Ac;
        float L01 = wy0 * Bm + (1.0f - wy0) * Bc;
        float L10 = wy1 * Ac + (1.0f - wy1) * Ap;
        float L11 = wy1 * Bc + (1.0f - wy1) * Bp;

        float ll = 0.25f * (L00 + L01 + L10 + L11);
        float lh = 0.25f * (L00 + L01 - L10 - L11);
        float hl = 0.25f * (L00 - L01 + L10 - L11);
        float hh = 0.25f * (L00 - L01 - L10 + L11);
        l12[u * 18 + v] = make_float2(ll, fabsf(lh) + fabsf(hl) + fabsf(hh));
    }
    __syncthreads();

    // ---------------- stage 4: epilogue (2 vertical quads / thread) ----------------
    const int qx = tid & 15;
    const int ph = tid >> 4;                 // 0..15
    const int q = (j0 >> 1) + qx;            // out cols 2q, 2q+1
    const int p0 = (i0 >> 1) + 2 * ph;       // out rows 2p0..2p0+3

    // --- hi0 resize (255->256): 5 rows x 3 cols, 2 row clamps ---
    int s0 = (clampi(2 * p0 - 1, 0, 254) - (i0 - 1)) * 20;
    int s1 = (4 * ph + 1) * 20;
    int s2 = s1 + 20, s3 = s1 + 40;
    int s4 = (clampi(2 * p0 + 3, 0, 254) - (i0 - 1)) * 20;

    float w0 = (2 * q + 0.5f) * INV256;
    float w1 = (2 * q + 1.5f) * INV256;

#define HCL(S, CA, CB)                                                        \
    {                                                                         \
        float ov = sm[HSO + (S) + qx], ev = sm[HSE + (S) + qx];               \
        float o2 = sm[HSO + (S) + qx + 1];                                    \
        CA = w0 * ov + (1.0f - w0) * ev;                                      \
        CB = w1 * ev + (1.0f - w1) * o2;                                      \
    }
    float cA0, cB0, cA1, cB1, cA2, cB2, cA3, cB3, cA4, cB4;
    HCL(s0, cA0, cB0) HCL(s1, cA1, cB1) HCL(s2, cA2, cB2)
    HCL(s3, cA3, cB3) HCL(s4, cA4, cB4)
#undef HCL

    float wy0 = (2 * p0 + 0.5f) * INV256;
    float wy1 = (2 * p0 + 1.5f) * INV256;
    float wy2 = (2 * p0 + 2.5f) * INV256;
    float wy3 = (2 * p0 + 3.5f) * INV256;

    float h0A0 = wy0 * cA0 + (1.0f - wy0) * cA1;
    float h0B0 = wy0 * cB0 + (1.0f - wy0) * cB1;
    float h0A1 = wy1 * cA1 + (1.0f - wy1) * cA2;
    float h0B1 = wy1 * cB1 + (1.0f - wy1) * cB2;
    float h0A2 = wy2 * cA2 + (1.0f - wy2) * cA3;
    float h0B2 = wy2 * cB2 + (1.0f - wy2) * cB3;
    float h0A3 = wy3 * cA3 + (1.0f - wy3) * cA4;
    float h0B3 = wy3 * cB3 + (1.0f - wy3) * cB4;

    // --- ll1/hi1 resize (128->256): float2 taps, 4 rows x 3 cols, pure ---
    const float2* l12c = reinterpret_cast<const float2*>(sm + L12);
    int t0 = 2 * ph * 18 + qx;
    int t1 = t0 + 18, t2 = t0 + 36, t3 = t0 + 54;

#define LERP2(O, WA, A, WB, B)                                                \
    { O.x = (WA) * A.x + (WB) * B.x; O.y = (WA) * A.y + (WB) * B.y; }

    float2 r0m = l12c[t0], r0c = l12c[t0 + 1], r0p = l12c[t0 + 2];
    float2 r1m = l12c[t1], r1c = l12c[t1 + 1], r1p = l12c[t1 + 2];
    float2 r2m = l12c[t2], r2c = l12c[t2 + 1], r2p = l12c[t2 + 2];
    float2 r3m = l12c[t3], r3c = l12c[t3 + 1], r3p = l12c[t3 + 2];

    float2 a0, b0, a1, b1, a2, b2, a3, b3;
    LERP2(a0, 0.25f, r0m, 0.75f, r0c) LERP2(b0, 0.75f, r0c, 0.25f, r0p)
    LERP2(a1, 0.25f, r1m, 0.75f, r1c) LERP2(b1, 0.75f, r1c, 0.25f, r1p)
    LERP2(a2, 0.25f, r2m, 0.75f, r2c) LERP2(b2, 0.75f, r2c, 0.25f, r2p)
    LERP2(a3, 0.25f, r3m, 0.75f, r3c) LERP2(b3, 0.75f, r3c, 0.25f, r3p)

    float2 vA0, vB0, vA1, vB1, vA2, vB2, vA3, vB3;
    LERP2(vA0, 0.25f, a0, 0.75f, a1) LERP2(vB0, 0.25f, b0, 0.75f, b1)
    LERP2(vA1, 0.75f, a1, 0.25f, a2) LERP2(vB1, 0.75f, b1, 0.25f, b2)
    LERP2(vA2, 0.25f, a1, 0.75f, a2) LERP2(vB2, 0.25f, b1, 0.75f, b2)
    LERP2(vA3, 0.75f, a2, 0.25f, a3) LERP2(vB3, 0.75f, b2, 0.25f, b3)
#undef LERP2

    // --- stores: rows 2p0..2p0+3, cols 2q..2q+1 ---
    const size_t nimg = (size_t)nc * IMG;
    float* out_low = out;
    float* out_high = out + nimg;
    size_t base = (size_t)ch * IMG + (size_t)(2 * p0) * HW + 2 * q;

    *reinterpret_cast<float2*>(out_low + base) = make_float2(vA0.x, vB0.x);
    *reinterpret_cast<float2*>(out_low + base + HW) = make_float2(vA1.x, vB1.x);
    *reinterpret_cast<float2*>(out_low + base + 2 * HW) = make_float2(vA2.x, vB2.x);
    *reinterpret_cast<float2*>(out_low + base + 3 * HW) = make_float2(vA3.x, vB3.x);
    *reinterpret_cast<float2*>(out_high + base) =
        make_float2(0.5f * (h0A0 + vA0.y), 0.5f * (h0B0 + vB0.y));
    *reinterpret_cast<float2*>(out_high + base + HW) =
        make_float2(0.5f * (h0A1 + vA1.y), 0.5f * (h0B1 + vB1.y));
    *reinterpret_cast<float2*>(out_high + base + 2 * HW) =
        make_float2(0.5f * (h0A2 + vA2.y), 0.5f * (h0B2 + vB2.y));
    *reinterpret_cast<float2*>(out_high + base + 3 * HW) =
        make_float2(0.5f * (h0A3 + vA3.y), 0.5f * (h0B3 + vB3.y));
}

extern "C" void kernel_launch(void* const* d_in, const int* in_sizes, int n_in,
                              void* d_out, int out_size) {
    const float* x = (const float*)d_in[0];
    float* out = (float*)d_out;
    int nc = in_sizes[0] / IMG;  // 512

    dim3 blk(256);
    dim3 grd(HW / 32, HW / 64, nc);
    k_fused<<<grd, blk>>>(x, out, nc);
}

// round 17
// speedup vs baseline: 1.0346x; 1.0260x over previous
#include <cuda_runtime.h>

// HaarWavelet2D level=2, x:(8,64,256,256) fp32 -> (low,high).
// One fused kernel, 64x32 output tile per 256-thread block.
// E/O column-split smem (conflict-free stride-2), clamp-at-load + reflect
// patch for pure downstream indexing. ll1/hi1 interleaved float2 (LDS.64),
// overlaid on the xs region (dead after stage 2).
// This round: LLE/LLO packed at stride 18/19, arrays packed tight ->
// SM_TOT = 7977 floats (31.9KB) -> 7 CTAs/SM.
//
// XE: even cols j0-4..j0+34 -> slots 0..19 (slot (c-j0+4)/2), stride 20
// XO: odd  cols j0-3..j0+35 -> slots 0..19 (slot (c-j0+3)/2), stride 20

#define HW 256
#define IMG (HW*HW)
#define INV256 (1.0f/256.0f)

// smem offsets (floats). XO-XE = 1424 ≡ 16 (mod 32).
#define XE 0
#define XO 1424
#define LLE 2824            // 69 rows x stride 18 = 1242
#define LLO 4066            // 69 rows x stride 19 = 1311
#define HSE 5377            // 65 rows x stride 20 = 1300
#define HSO 6677            // 65 rows x stride 20 = 1300
#define L12 0               // interleaved {ll1,hi1} float2, ALIASES xs region
#define SM_TOT 7977

__device__ __forceinline__ int clampi(int v, int lo, int hi) {
    return v < lo ? lo : (v > hi ? hi : v);
}

__global__ void __launch_bounds__(256, 7) k_fused(const float* __restrict__ x,
                                                  float* __restrict__ out, int nc) {
    __shared__ float sm[SM_TOT];

    const int ch = blockIdx.z;
    const int i0 = blockIdx.y * 64;
    const int j0 = blockIdx.x * 32;
    const int tid = threadIdx.x;
    const float* xc = x + (size_t)ch * IMG;

    // ---------------- stage 1: load x ----------------
    if (blockIdx.x != 0 && blockIdx.x != 7) {
        // interior: cols j0-4..j0+35 all in [0,255]; float2 loads (8B aligned).
        for (int e = tid; e < 70 * 20; e += 256) {
            int u = e / 20, m = e - u * 20;
            int gr = clampi(i0 - 3 + u, 0, 255);
            float2 v2 = *reinterpret_cast<const float2*>(xc + gr * HW + (j0 - 4 + 2 * m));
            sm[XE + u * 20 + m] = v2.x;   // even col j0-4+2m
            sm[XO + u * 20 + m] = v2.y;   // odd  col j0-3+2m
        }
    } else {
        // edge blocks: scalar with clamp + reflect patch.
        for (int e = tid; e < 70 * 38; e += 256) {
            int u = e / 38, v = e - u * 38;
            int gr = clampi(i0 - 3 + u, 0, 255);
            int g = j0 - 3 + v;
            int gc = clampi(g, 0, 255);
            if (g == -1) gc = 1;
            if (g == 256) gc = 254;
            float val = __ldg(xc + gr * HW + gc);
            // v odd -> even col g -> XE slot (v>>1)+1 ; v even -> odd col -> XO slot v>>1
            sm[((v & 1) ? (XE + 1) : XO) + u * 20 + (v >> 1)] = val;
        }
    }
    __syncthreads();

    // ---------------- stage 2: LL (ll0) + hi0, shared reads ----------------
    for (int e = tid; e < 69 * 19; e += 256) {
        int r = e / 19, w = e - r * 19;
        int ro = r * 20, r1 = ro + 20;
        float o0 = sm[XO + ro + w], e0 = sm[XE + ro + w + 1];
        float o1 = sm[XO + r1 + w], e1 = sm[XE + r1 + w + 1];

        // LLO point (odd col cO = j0-3+2w, and cO+1)
        float sA = o0 + e0, dA = o0 - e0;
        float sB = o1 + e1, dB = o1 - e1;
        sm[LLO + r * 19 + w] = 0.25f * (sA + sB);
        bool hrow = (r >= 2) && (r <= 66);
        int hb = (r - 2) * 20;
        if (hrow && w >= 1 && w <= 17)
            sm[HSO + hb + (w - 1)] =
                0.25f * (fabsf(sA - sB) + fabsf(dA + dB) + fabsf(dA - dB));

        if (w <= 17) {
            float p0 = sm[XO + ro + w + 1];
            float p1 = sm[XO + r1 + w + 1];
            // LLE point (even col cE = j0-2+2w, and cE+1)
            float sC = e0 + p0, dC = e0 - p0;
            float sD = e1 + p1, dD = e1 - p1;
            sm[LLE + r * 18 + w] = 0.25f * (sC + sD);
            if (hrow && w >= 1)
                sm[HSE + hb + (w - 1)] =
                    0.25f * (fabsf(sC - sD) + fabsf(dC + dD) + fabsf(dC - dD));
        }
    }
    __syncthreads();

    // ---------------- stage 3: ll1 / hi1 (writes alias dead xs region) ----------------
    const int A0 = (i0 >> 1) - 1;
    const int B0 = (j0 >> 1) - 1;
    float2* l12 = reinterpret_cast<float2*>(sm + L12);
    for (int e = tid; e < 34 * 18; e += 256) {
        int u = e / 18, v = e - u * 18;
        int a = clampi(A0 + u, 0, 127);
        int b = clampi(B0 + v, 0, 127);
        int d = b - B0;
        int rrm = clampi(2 * a - 1, 0, 254) - (i0 - 3);
        int rr0 = 2 * a - (i0 - 3);
        int rrp = clampi(2 * a + 1, 0, 254) - (i0 - 3);
        int rmO = rrm * 19, r0O = rr0 * 19, rpO = rrp * 19;
        int rmE = rrm * 18, r0E = rr0 * 18, rpE = rrp * 18;

        float m_m = sm[LLO + rmO + d], m_0 = sm[LLE + rmE + d], m_p = sm[LLO + rmO + d + 1];
        float c_m = sm[LLO + r0O + d], c_0 = sm[LLE + r0E + d], c_p = sm[LLO + r0O + d + 1];
        float p_m = sm[LLO + rpO + d], p_0 = sm[LLE + rpE + d], p_p = sm[LLO + rpO + d + 1];

        float wy0 = (2 * a + 0.5f) * INV256, wy1 = (2 * a + 1.5f) * INV256;
        float wx0 = (2 * b + 0.5f) * INV256, wx1 = (2 * b + 1.5f) * INV256;

        float Am = wx0 * m_m + (1.0f - wx0) * m_0;
        float Ac = wx0 * c_m + (1.0f - wx0) * c_0;
        float Ap = wx0 * p_m + (1.0f - wx0) * p_0;
        float Bm = wx1 * m_0 + (1.0f - wx1) * m_p;
        float Bc = wx1 * c_0 + (1.0f - wx1) * c_p;
        float Bp = wx1 * p_0 + (1.0f - wx1) * p_p;

        float L00 = wy0 * Am + (1.0f - wy0) * Ac;
        float L01 = wy0 * Bm + (1.0f - wy0) * Bc;
        float L10 = wy1 * Ac + (1.0f - wy1) * Ap;
        float L11 = wy1 * Bc + (1.0f - wy1) * Bp;

        float ll = 0.25f * (L00 + L01 + L10 + L11);
        float lh = 0.25f * (L00 + L01 - L10 - L11);
        float hl = 0.25f * (L00 - L01 + L10 - L11);
        float hh = 0.25f * (L00 - L01 - L10 + L11);
        l12[u * 18 + v] = make_float2(ll, fabsf(lh) + fabsf(hl) + fabsf(hh));
    }
    __syncthreads();

    // ---------------- stage 4: epilogue (2 vertical quads / thread) ----------------
    const int qx = tid & 15;
    const int ph = tid >> 4;                 // 0..15
    const int q = (j0 >> 1) + qx;            // out cols 2q, 2q+1
    const int p0 = (i0 >> 1) + 2 * ph;       // out rows 2p0..2p0+3

    // --- hi0 resize (255->256): 5 rows x 3 cols, 2 row clamps ---
    int s0 = (clampi(2 * p0 - 1, 0, 254) - (i0 - 1)) * 20;
    int s1 = (4 * ph + 1) * 20;
    int s2 = s1 + 20, s3 = s1 + 40;
    int s4 = (clampi(2 * p0 + 3, 0, 254) - (i0 - 1)) * 20;

    float w0 = (2 * q + 0.5f) * INV256;
    float w1 = (2 * q + 1.5f) * INV256;

#define HCL(S, CA, CB)                                                        \
    {                                                                         \
        float ov = sm[HSO + (S) + qx], ev = sm[HSE + (S) + qx];               \
        float o2 = sm[HSO + (S) + qx + 1];                                    \
        CA = w0 * ov + (1.0f - w0) * ev;                                      \
        CB = w1 * ev + (1.0f - w1) * o2;                                      \
    }
    float cA0, cB0, cA1, cB1, cA2, cB2, cA3, cB3, cA4, cB4;
    HCL(s0, cA0, cB0) HCL(s1, cA1, cB1) HCL(s2, cA2, cB2)
    HCL(s3, cA3, cB3) HCL(s4, cA4, cB4)
#undef HCL

    float wy0 = (2 * p0 + 0.5f) * INV256;
    float wy1 = (2 * p0 + 1.5f) * INV256;
    float wy2 = (2 * p0 + 2.5f) * INV256;
    float wy3 = (2 * p0 + 3.5f) * INV256;

    float h0A0 = wy0 * cA0 + (1.0f - wy0) * cA1;
    float h0B0 = wy0 * cB0 + (1.0f - wy0) * cB1;
    float h0A1 = wy1 * cA1 + (1.0f - wy1) * cA2;
    float h0B1 = wy1 * cB1 + (1.0f - wy1) * cB2;
    float h0A2 = wy2 * cA2 + (1.0f - wy2) * cA3;
    float h0B2 = wy2 * cB2 + (1.0f - wy2) * cB3;
    float h0A3 = wy3 * cA3 + (1.0f - wy3) * cA4;
    float h0B3 = wy3 * cB3 + (1.0f - wy3) * cB4;

    // --- ll1/hi1 resize (128->256): float2 taps, 4 rows x 3 cols, pure ---
    const float2* l12c = reinterpret_cast<const float2*>(sm + L12);
    int t0 = 2 * ph * 18 + qx;
    int t1 = t0 + 18, t2 = t0 + 36, t3 = t0 + 54;

#define LERP2(O, WA, A, WB, B)                                                \
    { O.x = (WA) * A.x + (WB) * B.x; O.y = (WA) * A.y + (WB) * B.y; }

    float2 r0m = l12c[t0], r0c = l12c[t0 + 1], r0p = l12c[t0 + 2];
    float2 r1m = l12c[t1], r1c = l12c[t1 + 1], r1p = l12c[t1 + 2];
    float2 r2m = l12c[t2], r2c = l12c[t2 + 1], r2p = l12c[t2 + 2];
    float2 r3m = l12c[t3], r3c = l12c[t3 + 1], r3p = l12c[t3 + 2];

    float2 a0, b0, a1, b1, a2, b2, a3, b3;
    LERP2(a0, 0.25f, r0m, 0.75f, r0c) LERP2(b0, 0.75f, r0c, 0.25f, r0p)
    LERP2(a1, 0.25f, r1m, 0.75f, r1c) LERP2(b1, 0.75f, r1c, 0.25f, r1p)
    LERP2(a2, 0.25f, r2m, 0.75f, r2c) LERP2(b2, 0.75f, r2c, 0.25f, r2p)
    LERP2(a3, 0.25f, r3m, 0.75f, r3c) LERP2(b3, 0.75f, r3c, 0.25f, r3p)

    float2 vA0, vB0, vA1, vB1, vA2, vB2, vA3, vB3;
    LERP2(vA0, 0.25f, a0, 0.75f, a1) LERP2(vB0, 0.25f, b0, 0.75f, b1)
    LERP2(vA1, 0.75f, a1, 0.25f, a2) LERP2(vB1, 0.75f, b1, 0.25f, b2)
    LERP2(vA2, 0.25f, a1, 0.75f, a2) LERP2(vB2, 0.25f, b1, 0.75f, b2)
    LERP2(vA3, 0.75f, a2, 0.25f, a3) LERP2(vB3, 0.75f, b2, 0.25f, b3)
#undef LERP2

    // --- stores: rows 2p0..2p0+3, cols 2q..2q+1 ---
    const size_t nimg = (size_t)nc * IMG;
    float* out_low = out;
    float* out_high = out + nimg;
    size_t base = (size_t)ch * IMG + (size_t)(2 * p0) * HW + 2 * q;

    *reinterpret_cast<float2*>(out_low + base) = make_float2(vA0.x, vB0.x);
    *reinterpret_cast<float2*>(out_low + base + HW) = make_float2(vA1.x, vB1.x);
    *reinterpret_cast<float2*>(out_low + base + 2 * HW) = make_float2(vA2.x, vB2.x);
    *reinterpret_cast<float2*>(out_low + base + 3 * HW) = make_float2(vA3.x, vB3.x);
    *reinterpret_cast<float2*>(out_high + base) =
        make_float2(0.5f * (h0A0 + vA0.y), 0.5f * (h0B0 + vB0.y));
    *reinterpret_cast<float2*>(out_high + base + HW) =
        make_float2(0.5f * (h0A1 + vA1.y), 0.5f * (h0B1 + vB1.y));
    *reinterpret_cast<float2*>(out_high + base + 2 * HW) =
        make_float2(0.5f * (h0A2 + vA2.y), 0.5f * (h0B2 + vB2.y));
    *reinterpret_cast<float2*>(out_high + base + 3 * HW) =
        make_float2(0.5f * (h0A3 + vA3.y), 0.5f * (h0B3 + vB3.y));
}

extern "C" void kernel_launch(void* const* d_in, const int* in_sizes, int n_in,
                              void* d_out, int out_size) {
    const float* x = (const float*)d_in[0];
    float* out = (float*)d_out;
    int nc = in_sizes[0] / IMG;  // 512

    dim3 blk(256);
    dim3 grd(HW / 32, HW / 64, nc);
    k_fused<<<grd, blk>>>(x, out, nc);
}